// round 7
// baseline (speedup 1.0000x reference)
#include <cuda_runtime.h>
#include <cuda_bf16.h>
#include <cstdint>

// embeddings [B=512, I=128, D=64] fp32
// out[b,i,d] = tanh( emb[b,i,d] * (1/I) * sum_j emb[b,j,d] )
//
// R7: 256-bit vector ld/st (ld.global.v8.f32 / st.global.v8.f32, sm_100+)
// on the best-measured R2 structure. One CTA per batch, 512 x 256 thr.
// Thread t: col-group g=t&7 (8 floats), row base rg=t>>3; 4 x ld256
// (rows rg+32k) held in regs -> input read from HBM exactly once.
// Warp shuffle xor(8,16) reduces the 4 rows-per-warp; 64-thread scalar
// final reduce -> mean[64]; tanh; 4 x st256. Memory-op count halved vs
// the float4 variants (warm path is issue/latency bound, not BW bound).

static constexpr int BATCH   = 512;
static constexpr int SEQ_I   = 128;
static constexpr int DIM     = 64;
static constexpr int GROUPS  = DIM / 8;   // 8 col-groups of 8 floats
static constexpr int THREADS = 256;

struct V8 { float f[8]; };

__device__ __forceinline__ void ldg256(V8& v, const float* p) {
    asm volatile("ld.global.v8.f32 {%0,%1,%2,%3,%4,%5,%6,%7}, [%8];"
                 : "=f"(v.f[0]), "=f"(v.f[1]), "=f"(v.f[2]), "=f"(v.f[3]),
                   "=f"(v.f[4]), "=f"(v.f[5]), "=f"(v.f[6]), "=f"(v.f[7])
                 : "l"(p));
}

__device__ __forceinline__ void stg256(float* p, const V8& v) {
    asm volatile("st.global.v8.f32 [%0], {%1,%2,%3,%4,%5,%6,%7,%8};"
                 :: "l"(p),
                    "f"(v.f[0]), "f"(v.f[1]), "f"(v.f[2]), "f"(v.f[3]),
                    "f"(v.f[4]), "f"(v.f[5]), "f"(v.f[6]), "f"(v.f[7])
                 : "memory");
}

__device__ __forceinline__ float fast_tanh(float x) {
    float y;
    asm("tanh.approx.f32 %0, %1;" : "=f"(y) : "f"(x));
    return y;
}

__global__ __launch_bounds__(THREADS, 4)
void ATT0_40707700032104_kernel(const float* __restrict__ in,
                                float* __restrict__ out) {
    const int b  = blockIdx.x;
    const int t  = threadIdx.x;
    const int g  = t & (GROUPS - 1);   // col-group (0..7), 8 floats each
    const int rg = t >> 3;             // row base (0..31)

    const size_t base = (size_t)b * (SEQ_I * DIM) + (size_t)g * 8;
    const float* src = in  + base;
    float*       dst = out + base;

    // ---- 4 independent LDG.E.256 (rows rg+32k), full tile in registers ----
    V8 v[4];
#pragma unroll
    for (int k = 0; k < 4; k++)
        ldg256(v[k], src + (size_t)(rg + 32 * k) * DIM);

    // ---- Per-thread column-group partial (8 floats) ----
    V8 s;
#pragma unroll
    for (int f = 0; f < 8; f++)
        s.f[f] = (v[0].f[f] + v[1].f[f]) + (v[2].f[f] + v[3].f[f]);

    // ---- Warp reduce: lanes l, l+8, l+16, l+24 share col-group g ----
#pragma unroll
    for (int off = 8; off <= 16; off <<= 1) {
#pragma unroll
        for (int f = 0; f < 8; f++)
            s.f[f] += __shfl_xor_sync(0xffffffffu, s.f[f], off);
    }

    // ---- Publish per-warp col-group sums (lanes 0..7 of each warp) ----
    __shared__ float wsum[8][GROUPS][8];   // [warp][group][float] 2 KB
    __shared__ float meanv[GROUPS][8];
    const int w    = t >> 5;
    const int lane = t & 31;
    if (lane < GROUPS) {
#pragma unroll
        for (int f = 0; f < 8; f++) wsum[w][lane][f] = s.f[f];
    }
    __syncthreads();

    // ---- 64-thread scalar final reduce: (group, float) pairs ----
    if (t < 64) {
        const int gg = t >> 3, ff = t & 7;
        float m = wsum[0][gg][ff];
#pragma unroll
        for (int ww = 1; ww < 8; ww++) m += wsum[ww][gg][ff];
        meanv[gg][ff] = m * (1.0f / (float)SEQ_I);
    }
    __syncthreads();

    float m[8];
#pragma unroll
    for (int f = 0; f < 8; f++) m[f] = meanv[g][f];

    // ---- tanh(v * mean) from registers, 4 x STG.E.256 ----
#pragma unroll
    for (int k = 0; k < 4; k++) {
        V8 r;
#pragma unroll
        for (int f = 0; f < 8; f++)
            r.f[f] = fast_tanh(v[k].f[f] * m[f]);
        stg256(dst + (size_t)(rg + 32 * k) * DIM, r);
    }
}

extern "C" void kernel_launch(void* const* d_in, const int* in_sizes, int n_in,
                              void* d_out, int out_size) {
    const float* in  = (const float*)d_in[0];
    float*       out = (float*)d_out;
    ATT0_40707700032104_kernel<<<BATCH, THREADS>>>(in, out);
}